// round 4
// baseline (speedup 1.0000x reference)
#include <cuda_runtime.h>
#include <cuda_bf16.h>
#include <cstdint>

#define DI __device__ __forceinline__

// Problem shape (fixed by the dataset)
static constexpr int M_TOTAL = 8192;   // B*S = 4*2048
static constexpr int N_TOTAL = 4096;
static constexpr int K_TOTAL = 1024;

// Packed int8 scratch (harness delivers int8 logical data as int32 buffers)
__device__ __align__(16) int8_t g_x8[(size_t)M_TOTAL * K_TOTAL];   // 8 MB
__device__ __align__(16) int8_t g_w8[(size_t)N_TOTAL * K_TOTAL];   // 4 MB

// Tiling
static constexpr int TILE_M  = 128;
static constexpr int TILE_N  = 128;
static constexpr int KSTAGE  = 64;                   // K per pipeline stage
static constexpr int NCHUNK  = K_TOTAL / KSTAGE;     // 16
static constexpr int NSTAGES = 4;
static constexpr int THREADS = 256;                  // 8 warps, 4(M) x 2(N)

// SMEM: int8 tiles, rows padded 64B -> 80B (20-bank stride => conflict-free LDS)
static constexpr int ROW_B   = 80;
static constexpr int A_STAGE = TILE_M * ROW_B;       // 10240 B
static constexpr int B_STAGE = TILE_N * ROW_B;       // 10240 B
static constexpr int SM_B0   = NSTAGES * A_STAGE;
static constexpr int SM_BYTES = NSTAGES * (A_STAGE + B_STAGE);  // 81920 B

DI uint32_t smem_u32(const void* p) {
    uint32_t a;
    asm("{ .reg .u64 t; cvta.to.shared.u64 t, %1; cvt.u32.u64 %0, t; }" : "=r"(a) : "l"(p));
    return a;
}
DI void cp16(uint32_t dst, const void* src) {
    asm volatile("cp.async.cg.shared.global [%0], [%1], 16;" :: "r"(dst), "l"(src));
}
#define CP_COMMIT() asm volatile("cp.async.commit_group;" ::: "memory")
#define CP_WAIT2()  asm volatile("cp.async.wait_group 2;" ::: "memory")

DI uint32_t lds32(uint32_t a) {
    uint32_t v;
    asm volatile("ld.shared.b32 %0, [%1];" : "=r"(v) : "r"(a));
    return v;
}

// IMMA: D(s32) = A(s8,row) * B(s8,col) + D.  A 16x32, B 32x8, C 16x8.
DI void mma_s8(int* c, const uint32_t* a, uint32_t b0, uint32_t b1) {
    asm volatile(
        "mma.sync.aligned.m16n8k32.row.col.s32.s8.s8.s32 "
        "{%0,%1,%2,%3}, {%4,%5,%6,%7}, {%8,%9}, {%0,%1,%2,%3};"
        : "+r"(c[0]), "+r"(c[1]), "+r"(c[2]), "+r"(c[3])
        : "r"(a[0]), "r"(a[1]), "r"(a[2]), "r"(a[3]), "r"(b0), "r"(b1));
}

// ---------------- Pack pre-pass: int32 -> int8, 16 elements/thread ----------------
DI uint32_t pack4(int4 v) {
    return (uint32_t)(v.x & 0xFF) | ((uint32_t)(v.y & 0xFF) << 8) |
           ((uint32_t)(v.z & 0xFF) << 16) | ((uint32_t)v.w << 24);
}
__global__ void pack_i32_to_i8(const int4* __restrict__ src, int8_t* __restrict__ dst, int n16) {
    int i = blockIdx.x * blockDim.x + threadIdx.x;
    if (i >= n16) return;
    const int4* p = src + (size_t)i * 4;
    uint4 o;
    o.x = pack4(p[0]); o.y = pack4(p[1]); o.z = pack4(p[2]); o.w = pack4(p[3]);
    reinterpret_cast<uint4*>(dst)[i] = o;
}

// Load one K-stage (64B per row) of A (128 rows) + B (128 rows) via cp.async.
DI void load_stage(const int8_t* __restrict__ x, const int8_t* __restrict__ w,
                   int m0, int n0, int kc, uint32_t sbase, int stage, int tid) {
    const uint32_t smA = sbase + stage * A_STAGE;
    const uint32_t smB = sbase + SM_B0 + stage * B_STAGE;
    const int k0 = kc * KSTAGE;
#pragma unroll
    for (int i = 0; i < 2; i++) {                    // 512 16B-chunks, 2/thread
        int u = tid + i * THREADS;
        int row = u >> 2, c = u & 3;
        cp16(smA + row * ROW_B + c * 16, x + (size_t)(m0 + row) * K_TOTAL + k0 + c * 16);
    }
#pragma unroll
    for (int i = 0; i < 2; i++) {
        int u = tid + i * THREADS;
        int row = u >> 2, c = u & 3;
        cp16(smB + row * ROW_B + c * 16, w + (size_t)(n0 + row) * K_TOTAL + k0 + c * 16);
    }
}

__global__ void __launch_bounds__(THREADS, 2)
qgemm_imma_kernel(const float* __restrict__ scale_i, const float* __restrict__ scale_w,
                  const float* __restrict__ bias, float* __restrict__ out) {
    extern __shared__ char smem[];
    const int8_t* __restrict__ x = g_x8;
    const int8_t* __restrict__ w = g_w8;
    const uint32_t sbase = smem_u32(smem);
    const int tid = threadIdx.x;
    const int lane = tid & 31;
    const int wid = tid >> 5;
    const int warp_m = wid & 3;        // 4 warps along M: 32 rows each
    const int warp_n = wid >> 2;       // 2 warps along N: 64 cols each
    const int m0 = blockIdx.y * TILE_M;
    const int n0 = blockIdx.x * TILE_N;

    const int tg = lane >> 2;          // groupID (0..7)
    const int tc = lane & 3;           // threadID_in_group

    int acc[2][8][4];
#pragma unroll
    for (int mt = 0; mt < 2; mt++)
#pragma unroll
        for (int nt = 0; nt < 8; nt++)
#pragma unroll
            for (int j = 0; j < 4; j++) acc[mt][nt][j] = 0;

    // Prologue: stages 0..2 in flight
    load_stage(x, w, m0, n0, 0, sbase, 0, tid); CP_COMMIT();
    load_stage(x, w, m0, n0, 1, sbase, 1, tid); CP_COMMIT();
    load_stage(x, w, m0, n0, 2, sbase, 2, tid); CP_COMMIT();

    const uint32_t aFragBase = sbase + (uint32_t)(warp_m * 32 + tg) * ROW_B + tc * 4;
    const uint32_t bFragBase = sbase + SM_B0 + (uint32_t)(warp_n * 64 + tg) * ROW_B + tc * 4;

#pragma unroll 1
    for (int kc = 0; kc < NCHUNK; kc++) {
        CP_WAIT2();                    // stage kc resident (pending <= 2)
        __syncthreads();
        if (kc + 3 < NCHUNK)
            load_stage(x, w, m0, n0, kc + 3, sbase, (kc + 3) & 3, tid);
        CP_COMMIT();

        const int stage = kc & 3;
        const uint32_t aS = aFragBase + stage * A_STAGE;
        const uint32_t bS = bFragBase + stage * B_STAGE;
#pragma unroll
        for (int ks = 0; ks < 2; ks++) {           // two k=32 steps per stage
            const uint32_t ko = ks * 32;
            uint32_t a[2][4];
#pragma unroll
            for (int mt = 0; mt < 2; mt++) {
                const uint32_t ab = aS + mt * 16 * ROW_B + ko;
                a[mt][0] = lds32(ab);               // (row g,    k lo)
                a[mt][1] = lds32(ab + 8 * ROW_B);   // (row g+8,  k lo)
                a[mt][2] = lds32(ab + 16);          // (row g,    k hi)
                a[mt][3] = lds32(ab + 8 * ROW_B + 16);
            }
#pragma unroll
            for (int nt = 0; nt < 8; nt++) {
                const uint32_t bb = bS + nt * 8 * ROW_B + ko;
                uint32_t b0 = lds32(bb);
                uint32_t b1 = lds32(bb + 16);
                mma_s8(acc[0][nt], a[0], b0, b1);
                mma_s8(acc[1][nt], a[1], b0, b1);
            }
        }
    }

    // Epilogue: out = float(acc) * (scale_i * scale_w[n]) + bias[n]  (exact: |acc| < 2^24)
    const float si = __ldg(scale_i);
    const int row0 = m0 + warp_m * 32 + tg;
    const int col0 = n0 + warp_n * 64 + tc * 2;
#pragma unroll
    for (int nt = 0; nt < 8; nt++) {
        const int c = col0 + nt * 8;
        const float2 sw = __ldg(reinterpret_cast<const float2*>(scale_w + c));
        const float2 bb = __ldg(reinterpret_cast<const float2*>(bias + c));
        const float s0 = si * sw.x, s1 = si * sw.y;
#pragma unroll
        for (int mt = 0; mt < 2; mt++) {
            const int r = row0 + mt * 16;
            float2 o0, o1;
            o0.x = fmaf((float)acc[mt][nt][0], s0, bb.x);
            o0.y = fmaf((float)acc[mt][nt][1], s1, bb.y);
            o1.x = fmaf((float)acc[mt][nt][2], s0, bb.x);
            o1.y = fmaf((float)acc[mt][nt][3], s1, bb.y);
            *reinterpret_cast<float2*>(out + (size_t)r * N_TOTAL + c)       = o0;
            *reinterpret_cast<float2*>(out + (size_t)(r + 8) * N_TOTAL + c) = o1;
        }
    }
}

extern "C" void kernel_launch(void* const* d_in, const int* in_sizes, int n_in,
                              void* d_out, int out_size) {
    // Harness promotes int8 jax arrays to int32 buffers (dtype universe: f32/i32/bf16).
    const int4* x32 = (const int4*)d_in[0];      // [8192,1024] int32 (values in [-128,127])
    const int4* w32 = (const int4*)d_in[1];      // [4096,1024] int32
    const float* si = (const float*)d_in[2];     // scalar f32
    const float* sw = (const float*)d_in[3];     // [4096] f32
    const float* bi = (const float*)d_in[4];     // [4096] f32
    float* out = (float*)d_out;                  // [8192,4096] f32

    int8_t *dx8 = nullptr, *dw8 = nullptr;
    cudaGetSymbolAddress((void**)&dx8, g_x8);
    cudaGetSymbolAddress((void**)&dw8, g_w8);

    // Pack pre-pass: 16 int32 -> 16 int8 per thread
    {
        int n16x = (M_TOTAL * K_TOTAL) / 16;     // 524288
        int n16w = (N_TOTAL * K_TOTAL) / 16;     // 262144
        pack_i32_to_i8<<<(n16x + 255) / 256, 256>>>(x32, dx8, n16x);
        pack_i32_to_i8<<<(n16w + 255) / 256, 256>>>(w32, dw8, n16w);
    }

    cudaFuncSetAttribute(qgemm_imma_kernel,
                         cudaFuncAttributeMaxDynamicSharedMemorySize, SM_BYTES);
    dim3 grid(N_TOTAL / TILE_N, M_TOTAL / TILE_M);  // (32, 64)
    qgemm_imma_kernel<<<grid, THREADS, SM_BYTES, 0>>>(si, sw, bi, out);
}

// round 6
// speedup vs baseline: 2.2816x; 2.2816x over previous
#include <cuda_runtime.h>
#include <cuda_bf16.h>
#include <cstdint>

#define DI __device__ __forceinline__

// Problem shape (fixed by the dataset)
static constexpr int M_TOTAL = 8192;   // B*S = 4*2048
static constexpr int N_TOTAL = 4096;
static constexpr int K_TOTAL = 1024;

// bf16 scratch (harness delivers int8 logical data promoted to int32 buffers;
// int8 values are exactly representable in bf16, fp32 accum is exact < 2^24)
__device__ __align__(16) uint16_t g_xh[(size_t)M_TOTAL * K_TOTAL];   // 16 MB
__device__ __align__(16) uint16_t g_wh[(size_t)N_TOTAL * K_TOTAL];   // 8 MB

// Tiling
static constexpr int TILE_M  = 128;
static constexpr int TILE_N  = 256;
static constexpr int KSTAGE  = 64;                   // K elems per stage (128 B/row bf16)
static constexpr int NCHUNK  = K_TOTAL / KSTAGE;     // 16
static constexpr int NSTAGES = 3;
static constexpr int THREADS = 512;                  // 16 warps: 4(M) x 4(N)

// SMEM: bf16 tiles, rows padded 128B -> 144B (stride 9 x 16B => conflict-free ldmatrix)
static constexpr int ROW_B   = 144;
static constexpr int A_STAGE = TILE_M * ROW_B;       // 18432 B
static constexpr int B_STAGE = TILE_N * ROW_B;       // 36864 B
static constexpr int SM_B0   = NSTAGES * A_STAGE;
static constexpr int SM_BYTES = NSTAGES * (A_STAGE + B_STAGE);  // 165888 B

DI uint32_t smem_u32(const void* p) {
    uint32_t a;
    asm("{ .reg .u64 t; cvta.to.shared.u64 t, %1; cvt.u32.u64 %0, t; }" : "=r"(a) : "l"(p));
    return a;
}
DI void cp16(uint32_t dst, const void* src) {
    asm volatile("cp.async.cg.shared.global [%0], [%1], 16;" :: "r"(dst), "l"(src));
}
#define CP_COMMIT() asm volatile("cp.async.commit_group;" ::: "memory")
#define CP_WAIT1()  asm volatile("cp.async.wait_group 1;" ::: "memory")

DI void ldsm4(uint32_t* r, uint32_t addr) {
    asm volatile("ldmatrix.sync.aligned.m8n8.x4.shared.b16 {%0,%1,%2,%3}, [%4];"
                 : "=r"(r[0]), "=r"(r[1]), "=r"(r[2]), "=r"(r[3]) : "r"(addr));
}

// HMMA bf16: D(f32) = A(bf16,row 16x16) * B(bf16,col 16x8) + D
DI void mma_bf16(float* c, const uint32_t* a, uint32_t b0, uint32_t b1) {
    asm volatile(
        "mma.sync.aligned.m16n8k16.row.col.f32.bf16.bf16.f32 "
        "{%0,%1,%2,%3}, {%4,%5,%6,%7}, {%8,%9}, {%0,%1,%2,%3};"
        : "+f"(c[0]), "+f"(c[1]), "+f"(c[2]), "+f"(c[3])
        : "r"(a[0]), "r"(a[1]), "r"(a[2]), "r"(a[3]), "r"(b0), "r"(b1));
}

// ---------------- Pack pre-pass: int32 -> bf16, 8 elements/thread ----------------
DI uint32_t bf16x2_from_ints(int lo, int hi) {
    uint32_t r;
    asm("cvt.rn.bf16x2.f32 %0, %1, %2;" : "=r"(r) : "f"((float)hi), "f"((float)lo));
    return r;
}
__global__ void pack_i32_to_bf16(const int4* __restrict__ src, uint16_t* __restrict__ dst, int n8) {
    int i = blockIdx.x * blockDim.x + threadIdx.x;
    if (i >= n8) return;
    int4 v0 = src[(size_t)i * 2 + 0];
    int4 v1 = src[(size_t)i * 2 + 1];
    uint4 o;
    o.x = bf16x2_from_ints(v0.x, v0.y);
    o.y = bf16x2_from_ints(v0.z, v0.w);
    o.z = bf16x2_from_ints(v1.x, v1.y);
    o.w = bf16x2_from_ints(v1.z, v1.w);
    reinterpret_cast<uint4*>(dst)[i] = o;
}

// Load one K-stage: A 128 rows + B 256 rows, 128B/row, via cp.async.
DI void load_stage(const uint16_t* __restrict__ x, const uint16_t* __restrict__ w,
                   int m0, int n0, int kc, uint32_t sbase, int stage, int tid) {
    const uint32_t smA = sbase + stage * A_STAGE;
    const uint32_t smB = sbase + SM_B0 + stage * B_STAGE;
    const int k0 = kc * KSTAGE;
#pragma unroll
    for (int i = 0; i < 2; i++) {                    // A: 1024 16B-chunks, 2/thread
        int u = tid + i * THREADS;
        int row = u >> 3, c = u & 7;
        cp16(smA + row * ROW_B + c * 16, x + (size_t)(m0 + row) * K_TOTAL + k0 + c * 8);
    }
#pragma unroll
    for (int i = 0; i < 4; i++) {                    // B: 2048 16B-chunks, 4/thread
        int u = tid + i * THREADS;
        int row = u >> 3, c = u & 7;
        cp16(smB + row * ROW_B + c * 16, w + (size_t)(n0 + row) * K_TOTAL + k0 + c * 8);
    }
}

__global__ void __launch_bounds__(THREADS, 1)
qgemm_hmma_kernel(const float* __restrict__ scale_i, const float* __restrict__ scale_w,
                  const float* __restrict__ bias, float* __restrict__ out) {
    extern __shared__ char smem[];
    const uint16_t* __restrict__ x = g_xh;
    const uint16_t* __restrict__ w = g_wh;
    const uint32_t sbase = smem_u32(smem);
    const int tid = threadIdx.x;
    const int lane = tid & 31;
    const int wid = tid >> 5;
    const int warp_m = wid & 3;        // 4 warps along M: 32 rows each
    const int warp_n = wid >> 2;       // 4 warps along N: 64 cols each
    const int m0 = blockIdx.y * TILE_M;
    const int n0 = blockIdx.x * TILE_N;

    const int tg = lane >> 2;          // groupID (0..7)
    const int tc = lane & 3;           // threadID_in_group

    float acc[2][8][4];
#pragma unroll
    for (int mt = 0; mt < 2; mt++)
#pragma unroll
        for (int nt = 0; nt < 8; nt++)
#pragma unroll
            for (int j = 0; j < 4; j++) acc[mt][nt][j] = 0.0f;

    // ldmatrix lane addressing (within a stage, before k-step offset):
    // A x4: matrices = [rows 0-7, k0-7][rows 8-15, k0-7][rows 0-7, k8-15][rows 8-15, k8-15]
    const int am = lane >> 3;
    const uint32_t aRow = (uint32_t)(warp_m * 32 + (am & 1) * 8 + (lane & 7));
    const uint32_t aOff = aRow * ROW_B + (uint32_t)(am >> 1) * 16;
    // B x4 per n-tile pair p: [n 0-7, k0-7][n 0-7, k8-15][n 8-15, k0-7][n 8-15, k8-15]
    const uint32_t bRow = (uint32_t)(warp_n * 64 + (am >> 1) * 8 + (lane & 7));
    const uint32_t bOff = bRow * ROW_B + (uint32_t)(am & 1) * 16;

    // Prologue: stages 0,1 in flight
    load_stage(x, w, m0, n0, 0, sbase, 0, tid); CP_COMMIT();
    load_stage(x, w, m0, n0, 1, sbase, 1, tid); CP_COMMIT();

#pragma unroll 1
    for (int kc = 0; kc < NCHUNK; kc++) {
        CP_WAIT1();                    // stage kc resident
        __syncthreads();               // all warps done with stage (kc+2)%3's old data
        if (kc + 2 < NCHUNK)
            load_stage(x, w, m0, n0, kc + 2, sbase, (kc + 2) % NSTAGES, tid);
        CP_COMMIT();

        const int stage = kc % NSTAGES;
        const uint32_t aS = sbase + stage * A_STAGE + aOff;
        const uint32_t bS = sbase + SM_B0 + stage * B_STAGE + bOff;
#pragma unroll
        for (int ks = 0; ks < 4; ks++) {           // four k=16 steps per stage
            const uint32_t ko = ks * 32;           // 16 bf16 = 32 bytes
            uint32_t a[2][4];
            ldsm4(a[0], aS + ko);
            ldsm4(a[1], aS + 16 * ROW_B + ko);
#pragma unroll
            for (int p = 0; p < 4; p++) {          // n-tile pairs (2p, 2p+1)
                uint32_t b[4];
                ldsm4(b, bS + (uint32_t)p * 16 * ROW_B + ko);
                mma_bf16(acc[0][2 * p + 0], a[0], b[0], b[1]);
                mma_bf16(acc[1][2 * p + 0], a[1], b[0], b[1]);
                mma_bf16(acc[0][2 * p + 1], a[0], b[2], b[3]);
                mma_bf16(acc[1][2 * p + 1], a[1], b[2], b[3]);
            }
        }
    }

    // Epilogue: out = acc * (scale_i * scale_w[n]) + bias[n]   (acc holds exact integers)
    const float si = __ldg(scale_i);
    const int row0 = m0 + warp_m * 32 + tg;
    const int col0 = n0 + warp_n * 64 + tc * 2;
#pragma unroll
    for (int nt = 0; nt < 8; nt++) {
        const int c = col0 + nt * 8;
        const float2 sw = __ldg(reinterpret_cast<const float2*>(scale_w + c));
        const float2 bb = __ldg(reinterpret_cast<const float2*>(bias + c));
        const float s0 = si * sw.x, s1 = si * sw.y;
#pragma unroll
        for (int mt = 0; mt < 2; mt++) {
            const int r = row0 + mt * 16;
            float2 o0, o1;
            o0.x = fmaf(acc[mt][nt][0], s0, bb.x);
            o0.y = fmaf(acc[mt][nt][1], s1, bb.y);
            o1.x = fmaf(acc[mt][nt][2], s0, bb.x);
            o1.y = fmaf(acc[mt][nt][3], s1, bb.y);
            *reinterpret_cast<float2*>(out + (size_t)r * N_TOTAL + c)       = o0;
            *reinterpret_cast<float2*>(out + (size_t)(r + 8) * N_TOTAL + c) = o1;
        }
    }
}

extern "C" void kernel_launch(void* const* d_in, const int* in_sizes, int n_in,
                              void* d_out, int out_size) {
    // Harness promotes int8 jax arrays to int32 buffers.
    const int4* x32 = (const int4*)d_in[0];      // [8192,1024] int32 (values in [-128,127])
    const int4* w32 = (const int4*)d_in[1];      // [4096,1024] int32
    const float* si = (const float*)d_in[2];     // scalar f32
    const float* sw = (const float*)d_in[3];     // [4096] f32
    const float* bi = (const float*)d_in[4];     // [4096] f32
    float* out = (float*)d_out;                  // [8192,4096] f32

    uint16_t *dxh = nullptr, *dwh = nullptr;
    cudaGetSymbolAddress((void**)&dxh, g_xh);
    cudaGetSymbolAddress((void**)&dwh, g_wh);

    {
        int n8x = (M_TOTAL * K_TOTAL) / 8;       // 1048576
        int n8w = (N_TOTAL * K_TOTAL) / 8;       // 524288
        pack_i32_to_bf16<<<(n8x + 255) / 256, 256>>>(x32, dxh, n8x);
        pack_i32_to_bf16<<<(n8w + 255) / 256, 256>>>(w32, dwh, n8w);
    }

    cudaFuncSetAttribute(qgemm_hmma_kernel,
                         cudaFuncAttributeMaxDynamicSharedMemorySize, SM_BYTES);
    dim3 grid(N_TOTAL / TILE_N, M_TOTAL / TILE_M);  // (16, 64)
    qgemm_hmma_kernel<<<grid, THREADS, SM_BYTES, 0>>>(si, sw, bi, out);
}